// round 6
// baseline (speedup 1.0000x reference)
#include <cuda_runtime.h>
#include <cstdint>
#include <math.h>

#define NB 16384
#define NS 2048
#define ND 512
#define NM (NB + NS)   // 18432 rows: [x ; samples]

// ---------------------------------------------------------------------------
// Scratch (__device__ globals — allocation-free contract)
// ---------------------------------------------------------------------------
__device__ __align__(16) float g_cat  [NM * ND];             // [rx ; rsm] rounded
__device__ __align__(16) float g_tmp1 [NM * ND];             // dml hidden
__device__ __align__(16) float g_dml  [NM * ND];             // [x_dml ; sam_new]
__device__ __align__(16) float g_K    [(long long)NB * NS];
__device__ __align__(16) float g_H    [(long long)NB * NS];
__device__ __align__(16) float g_nrm  [NM];                  // [nx ; ns]
__device__ __align__(16) float g_rW1  [ND * ND];
__device__ __align__(16) float g_rW2  [ND * ND];
__device__ __align__(16) float g_rWn1 [NS * NS];
__device__ __align__(16) float g_rWn2 [NS * NS];

// ---------------------------------------------------------------------------
// Helpers
// ---------------------------------------------------------------------------
__device__ __forceinline__ uint32_t smem_u32(const void* p) {
    uint32_t a;
    asm("{ .reg .u64 t; cvta.to.shared.u64 t, %1; cvt.u32.u64 %0, t; }" : "=r"(a) : "l"(p));
    return a;
}
__device__ __forceinline__ float tf32_rna(float x) {
    uint32_t r;
    asm("cvt.rna.tf32.f32 %0, %1;" : "=r"(r) : "f"(x));
    return __uint_as_float(r);
}
__device__ __forceinline__ float mish_f(float z) {
    float sp = (z > 20.0f) ? z : log1pf(expf(z));
    return z * tanhf(sp);
}
__device__ __forceinline__ void cp_async16(uint32_t saddr, const void* gaddr) {
    asm volatile("cp.async.cg.shared.global [%0], [%1], 16;" :: "r"(saddr), "l"(gaddr) : "memory");
}
__device__ __forceinline__ void cp_commit() {
    asm volatile("cp.async.commit_group;" ::: "memory");
}
__device__ __forceinline__ void ldsm4(uint32_t* d, uint32_t addr) {
    asm volatile("ldmatrix.sync.aligned.m8n8.x4.shared.b16 {%0,%1,%2,%3}, [%4];"
                 : "=r"(d[0]), "=r"(d[1]), "=r"(d[2]), "=r"(d[3]) : "r"(addr));
}
__device__ __forceinline__ void mma_tf32(float* c, const uint32_t* a, uint32_t b0, uint32_t b1) {
    asm volatile("mma.sync.aligned.m16n8k8.row.col.f32.tf32.tf32.f32 "
                 "{%0,%1,%2,%3}, {%4,%5,%6,%7}, {%8,%9}, {%0,%1,%2,%3};"
                 : "+f"(c[0]), "+f"(c[1]), "+f"(c[2]), "+f"(c[3])
                 : "r"(a[0]), "r"(a[1]), "r"(a[2]), "r"(a[3]), "r"(b0), "r"(b1));
}

enum { EPI_NONE = 0, EPI_BIAS = 1, EPI_BIAS_MISH = 2, EPI_MISH = 3, EPI_RBF = 4 };
enum { ST_RAW = 0, ST_ROUND = 1 };

// ---------------------------------------------------------------------------
// tf32 mma.sync GEMM:  C[M,N] = A[M,K] * B[N,K]^T (both row-major, K-major)
// CTA 256x128, 16 warps (8m x 2n) of 32x64 warp tiles. BK=32, 3-stage
// cp.async, 144KB smem, 1 CTA/SM.
// ---------------------------------------------------------------------------
#define A_BY     32768
#define STAGE_BY 49152
#define DSMEM_BY (3 * STAGE_BY)

template <int EPI, int STOREMODE>
__global__ void __launch_bounds__(512, 1)
gemm_mma(const float* __restrict__ Ah, const float* __restrict__ Bh,
         float* __restrict__ Ch,
         int M, int N, int K,
         const float* __restrict__ e1, const float* __restrict__ e2)
{
    extern __shared__ float smem[];
    const uint32_t sbase = smem_u32(smem);

    const int tid  = threadIdx.x;
    const int wid  = tid >> 5;
    const int lane = tid & 31;
    const int wm   = wid >> 1;
    const int wn   = wid & 1;
    const int nk   = K >> 5;

    const uint32_t rowA0 = blockIdx.y * 256;
    const uint32_t rowB0 = blockIdx.x * 128;

    uint32_t sAOff[4], gAo[4], sBOff[2], gBo[2];
#pragma unroll
    for (int i = 0; i < 4; i++) {
        int c = tid + i * 512, row = c >> 3, ch = c & 7;
        sAOff[i] = (uint32_t)((row * 8 + (ch ^ (row & 7))) * 16);
        gAo[i]   = (rowA0 + row) * (uint32_t)K + ch * 4;
    }
#pragma unroll
    for (int i = 0; i < 2; i++) {
        int c = tid + i * 512, row = c >> 3, ch = c & 7;
        sBOff[i] = (uint32_t)((row * 8 + (ch ^ (row & 7))) * 16);
        gBo[i]   = (rowB0 + row) * (uint32_t)K + ch * 4;
    }

    auto issue = [&](int fi) {
        const int s = fi % 3;
        const uint32_t k0 = (uint32_t)fi * 32;
        const uint32_t sA = sbase + s * STAGE_BY;
        const uint32_t sB = sA + A_BY;
#pragma unroll
        for (int i = 0; i < 4; i++) cp_async16(sA + sAOff[i], Ah + gAo[i] + k0);
#pragma unroll
        for (int i = 0; i < 2; i++) cp_async16(sB + sBOff[i], Bh + gBo[i] + k0);
        cp_commit();
    };

    const int r8    = lane & 7;
    const int matId = lane >> 3;
    const int mrow  = ((matId & 1) << 3) + r8;
    const int mhi   = matId >> 1;
    uint32_t csw[4], aRow[2], bRow[4];
#pragma unroll
    for (int ks = 0; ks < 4; ks++) csw[ks] = (uint32_t)(((2 * ks + mhi) ^ r8) << 4);
#pragma unroll
    for (int t = 0; t < 2; t++) aRow[t] = (uint32_t)((wm * 32 + t * 16 + mrow) * 128);
#pragma unroll
    for (int t = 0; t < 4; t++) bRow[t] = (uint32_t)((wn * 64 + t * 16 + mrow) * 128) + A_BY;

    float acc[2][8][4];
#pragma unroll
    for (int mt = 0; mt < 2; mt++)
#pragma unroll
        for (int nt = 0; nt < 8; nt++)
#pragma unroll
            for (int q = 0; q < 4; q++) acc[mt][nt][q] = 0.0f;

    issue(0);
    issue(1);

#pragma unroll 1
    for (int fi = 0; fi < nk; ++fi) {
        if (fi + 1 < nk) asm volatile("cp.async.wait_group 1;" ::: "memory");
        else             asm volatile("cp.async.wait_group 0;" ::: "memory");
        __syncthreads();
        if (fi + 2 < nk) issue(fi + 2);

        const uint32_t st = sbase + (fi % 3) * STAGE_BY;
#pragma unroll
        for (int ks = 0; ks < 4; ks++) {
            uint32_t a[2][4], bb[4][4];
#pragma unroll
            for (int mt = 0; mt < 2; mt++) ldsm4(a[mt],  st + aRow[mt] + csw[ks]);
#pragma unroll
            for (int np = 0; np < 4; np++) ldsm4(bb[np], st + bRow[np] + csw[ks]);
#pragma unroll
            for (int mt = 0; mt < 2; mt++)
#pragma unroll
                for (int nt = 0; nt < 8; nt++)
                    mma_tf32(acc[mt][nt], a[mt], bb[nt >> 1][nt & 1], bb[nt >> 1][2 + (nt & 1)]);
        }
    }

    const int gid = lane >> 2, tig = lane & 3;
#pragma unroll
    for (int mt = 0; mt < 2; mt++) {
        const int row = blockIdx.y * 256 + wm * 32 + mt * 16 + gid;
        float nr0 = 0.0f, nr8 = 0.0f;
        if (EPI == EPI_RBF) { nr0 = __ldg(e1 + row); nr8 = __ldg(e1 + row + 8); }
#pragma unroll
        for (int nt = 0; nt < 8; nt++) {
            const int col = blockIdx.x * 128 + wn * 64 + nt * 8 + tig * 2;
            float ec0 = 0.0f, ec1 = 0.0f;
            if (EPI == EPI_BIAS || EPI == EPI_BIAS_MISH || EPI == EPI_RBF) {
                const float* ee = (EPI == EPI_RBF) ? e2 : e1;
                ec0 = __ldg(ee + col); ec1 = __ldg(ee + col + 1);
            }
            float v[4] = {acc[mt][nt][0], acc[mt][nt][1], acc[mt][nt][2], acc[mt][nt][3]};
#pragma unroll
            for (int q = 0; q < 4; q++) {
                const float ec = (q & 1) ? ec1 : ec0;
                const float nr = (q < 2) ? nr0 : nr8;
                if (EPI == EPI_BIAS)           v[q] = v[q] + ec;
                else if (EPI == EPI_BIAS_MISH) v[q] = mish_f(v[q] + ec);
                else if (EPI == EPI_MISH)      v[q] = mish_f(v[q]);
                else if (EPI == EPI_RBF) {
                    float d2 = nr + ec - 2.0f * v[q];
                    v[q] = expf(-sqrtf(fmaxf(d2, 0.0f)));
                }
                if (STOREMODE == ST_ROUND) v[q] = tf32_rna(v[q]);
            }
            *(float2*)(Ch + (size_t)row * N + col)       = make_float2(v[0], v[1]);
            *(float2*)(Ch + (size_t)(row + 8) * N + col) = make_float2(v[2], v[3]);
        }
    }
}

// ---------------------------------------------------------------------------
// tf32 round copy + row squared-norms
// ---------------------------------------------------------------------------
__global__ void __launch_bounds__(256)
round_tf32_k(const float4* __restrict__ in, float4* __restrict__ out, int n4)
{
    int i = blockIdx.x * 256 + threadIdx.x;
    if (i < n4) {
        float4 v = in[i];
        v.x = tf32_rna(v.x); v.y = tf32_rna(v.y);
        v.z = tf32_rna(v.z); v.w = tf32_rna(v.w);
        out[i] = v;
    }
}

__global__ void __launch_bounds__(128)
rownorm2(const float* __restrict__ X, float* __restrict__ out)
{
    const int row = blockIdx.x;
    const float4 v = *((const float4*)(X + (size_t)row * ND) + threadIdx.x);
    float s = v.x * v.x + v.y * v.y + v.z * v.z + v.w * v.w;
#pragma unroll
    for (int o = 16; o; o >>= 1) s += __shfl_down_sync(0xffffffffu, s, o);
    __shared__ float ws[4];
    const int lane = threadIdx.x & 31, w = threadIdx.x >> 5;
    if (lane == 0) ws[w] = s;
    __syncthreads();
    if (threadIdx.x == 0) out[row] = ws[0] + ws[1] + ws[2] + ws[3];
}

// ---------------------------------------------------------------------------
// Launch — ncu captures GLOBAL launch #5 = harness(2) + ours index 3.
// Index 3 is the fused dml layer-1 GEMM (M=18432).
// ---------------------------------------------------------------------------
extern "C" void kernel_launch(void* const* d_in, const int* in_sizes, int n_in,
                              void* d_out, int out_size)
{
    const float* x   = (const float*)d_in[0];
    const float* sm  = (const float*)d_in[1];
    const float* W1  = (const float*)d_in[2];
    const float* b1  = (const float*)d_in[3];
    const float* W2  = (const float*)d_in[4];
    const float* b2  = (const float*)d_in[5];
    const float* Wn1 = (const float*)d_in[6];
    const float* Wn2 = (const float*)d_in[7];
    float* out = (float*)d_out;

    float *cat, *tmp1, *dml, *Kb, *Hb, *nrm, *rW1, *rW2, *rWn1, *rWn2;
    cudaGetSymbolAddress((void**)&cat,  g_cat);
    cudaGetSymbolAddress((void**)&tmp1, g_tmp1);
    cudaGetSymbolAddress((void**)&dml,  g_dml);
    cudaGetSymbolAddress((void**)&Kb,   g_K);
    cudaGetSymbolAddress((void**)&Hb,   g_H);
    cudaGetSymbolAddress((void**)&nrm,  g_nrm);
    cudaGetSymbolAddress((void**)&rW1,  g_rW1);
    cudaGetSymbolAddress((void**)&rW2,  g_rW2);
    cudaGetSymbolAddress((void**)&rWn1, g_rWn1);
    cudaGetSymbolAddress((void**)&rWn2, g_rWn2);

    cudaFuncSetAttribute(gemm_mma<EPI_BIAS_MISH, ST_ROUND>, cudaFuncAttributeMaxDynamicSharedMemorySize, DSMEM_BY);
    cudaFuncSetAttribute(gemm_mma<EPI_BIAS,      ST_ROUND>, cudaFuncAttributeMaxDynamicSharedMemorySize, DSMEM_BY);
    cudaFuncSetAttribute(gemm_mma<EPI_RBF,       ST_ROUND>, cudaFuncAttributeMaxDynamicSharedMemorySize, DSMEM_BY);
    cudaFuncSetAttribute(gemm_mma<EPI_MISH,      ST_ROUND>, cudaFuncAttributeMaxDynamicSharedMemorySize, DSMEM_BY);
    cudaFuncSetAttribute(gemm_mma<EPI_NONE,      ST_RAW  >, cudaFuncAttributeMaxDynamicSharedMemorySize, DSMEM_BY);

    const dim3 blk(512);

    // idx 0..2: rounding prerequisites for the captured GEMM
    round_tf32_k<<<NB * ND / 4 / 256, 256>>>((const float4*)x,  (float4*)cat,               NB * ND / 4);
    round_tf32_k<<<NS * ND / 4 / 256, 256>>>((const float4*)sm, (float4*)(cat + NB * ND),   NS * ND / 4);
    round_tf32_k<<<ND * ND / 4 / 256, 256>>>((const float4*)W1, (float4*)rW1,               ND * ND / 4);

    // idx 3: fused dml layer 1 (x + samples together) — ncu capture target
    gemm_mma<EPI_BIAS_MISH, ST_ROUND><<<dim3(ND / 128, NM / 256), blk, DSMEM_BY>>>(
        cat, rW1, tmp1, NM, ND, ND, b1, nullptr);

    round_tf32_k<<<ND * ND / 4 / 256, 256>>>((const float4*)W2, (float4*)rW2, ND * ND / 4);

    // dml layer 2 (fused)
    gemm_mma<EPI_BIAS, ST_ROUND><<<dim3(ND / 128, NM / 256), blk, DSMEM_BY>>>(
        tmp1, rW2, dml, NM, ND, ND, b2, nullptr);
    rownorm2<<<NM, 128>>>(dml, nrm);

    round_tf32_k<<<NS * NS / 4 / 256, 256>>>((const float4*)Wn1, (float4*)rWn1, NS * NS / 4);

    // K = exp(-sqrt(max(nx + ns - 2*x_dml@sam^T, 0)))
    gemm_mma<EPI_RBF, ST_ROUND><<<dim3(NS / 128, NB / 256), blk, DSMEM_BY>>>(
        dml, dml + (size_t)NB * ND, Kb, NB, NS, ND, nrm, nrm + NB);

    // h = mish(K @ Wn1^T)
    gemm_mma<EPI_MISH, ST_ROUND><<<dim3(NS / 128, NB / 256), blk, DSMEM_BY>>>(
        Kb, rWn1, Hb, NB, NS, NS, nullptr, nullptr);

    round_tf32_k<<<NS * NS / 4 / 256, 256>>>((const float4*)Wn2, (float4*)rWn2, NS * NS / 4);

    // out = h @ Wn2^T
    gemm_mma<EPI_NONE, ST_RAW><<<dim3(NS / 128, NB / 256), blk, DSMEM_BY>>>(
        Hb, rWn2, out, NB, NS, NS, nullptr, nullptr);
}

// round 7
// speedup vs baseline: 1.5483x; 1.5483x over previous
#include <cuda_runtime.h>
#include <cstdint>
#include <math.h>

#define NB 16384
#define NS 2048
#define ND 512
#define NM (NB + NS)   // 18432 rows: [x ; samples]

// ---------------------------------------------------------------------------
// Scratch (__device__ globals — allocation-free contract)
// ---------------------------------------------------------------------------
__device__ __align__(16) float g_cat  [NM * ND];             // [rx ; rsm] rounded
__device__ __align__(16) float g_tmp1 [NM * ND];             // dml hidden
__device__ __align__(16) float g_dml  [NM * ND];             // [x_dml ; sam_new]
__device__ __align__(16) float g_K    [(long long)NB * NS];
__device__ __align__(16) float g_H    [(long long)NB * NS];
__device__ __align__(16) float g_nrm  [NM];                  // [nx ; ns]
__device__ __align__(16) float g_rW1  [ND * ND];
__device__ __align__(16) float g_rW2  [ND * ND];
__device__ __align__(16) float g_rWn1 [NS * NS];
__device__ __align__(16) float g_rWn2 [NS * NS];

// ---------------------------------------------------------------------------
// Helpers
// ---------------------------------------------------------------------------
__device__ __forceinline__ uint32_t smem_u32(const void* p) {
    uint32_t a;
    asm("{ .reg .u64 t; cvta.to.shared.u64 t, %1; cvt.u32.u64 %0, t; }" : "=r"(a) : "l"(p));
    return a;
}
__device__ __forceinline__ float tf32_rna(float x) {
    uint32_t r;
    asm("cvt.rna.tf32.f32 %0, %1;" : "=r"(r) : "f"(x));
    return __uint_as_float(r);
}
__device__ __forceinline__ float mish_f(float z) {
    float sp = (z > 20.0f) ? z : log1pf(expf(z));
    return z * tanhf(sp);
}
__device__ __forceinline__ void cp_async16(uint32_t saddr, const void* gaddr) {
    asm volatile("cp.async.cg.shared.global [%0], [%1], 16;" :: "r"(saddr), "l"(gaddr) : "memory");
}
__device__ __forceinline__ void cp_commit() {
    asm volatile("cp.async.commit_group;" ::: "memory");
}
__device__ __forceinline__ void ldsm4(uint32_t* d, uint32_t addr) {
    asm volatile("ldmatrix.sync.aligned.m8n8.x4.shared.b16 {%0,%1,%2,%3}, [%4];"
                 : "=r"(d[0]), "=r"(d[1]), "=r"(d[2]), "=r"(d[3]) : "r"(addr));
}
__device__ __forceinline__ void mma_tf32(float* c, const uint32_t* a, uint32_t b0, uint32_t b1) {
    asm volatile("mma.sync.aligned.m16n8k8.row.col.f32.tf32.tf32.f32 "
                 "{%0,%1,%2,%3}, {%4,%5,%6,%7}, {%8,%9}, {%0,%1,%2,%3};"
                 : "+f"(c[0]), "+f"(c[1]), "+f"(c[2]), "+f"(c[3])
                 : "r"(a[0]), "r"(a[1]), "r"(a[2]), "r"(a[3]), "r"(b0), "r"(b1));
}

enum { EPI_NONE = 0, EPI_BIAS = 1, EPI_BIAS_MISH = 2, EPI_MISH = 3, EPI_RBF = 4 };
enum { ST_RAW = 0, ST_ROUND = 1 };

// ---------------------------------------------------------------------------
// tf32 mma.sync GEMM:  C[M,N] = A[M,K] * B[N,K]^T (both row-major, K-major)
// CTA 128x128, 8 warps (2m x 4n) of 64x32 warp tiles. BK=32, 3-stage cp.async,
// 96KB smem -> 2 CTAs/SM (measured-best config: interleaved CTAs hide
// barrier/ldsm stalls; kernel is issue-bound, not memory-bound).
// ---------------------------------------------------------------------------
#define A_BY     16384           // 128 rows * 128B
#define STAGE_BY 32768           // A + B
#define DSMEM_BY (3 * STAGE_BY)  // 98304

template <int EPI, int STOREMODE>
__global__ void __launch_bounds__(256, 2)
gemm_mma(const float* __restrict__ Ah, const float* __restrict__ Bh,
         float* __restrict__ Ch,
         int M, int N, int K,
         const float* __restrict__ e1, const float* __restrict__ e2)
{
    extern __shared__ float smem[];
    const uint32_t sbase = smem_u32(smem);

    const int tid  = threadIdx.x;
    const int wid  = tid >> 5;
    const int lane = tid & 31;
    const int wm   = wid & 1;        // 0..1 (64 rows each)
    const int wn   = wid >> 1;       // 0..3 (32 cols each)
    const int nk   = K >> 5;

    const uint32_t rowA0 = blockIdx.y * 128;
    const uint32_t rowB0 = blockIdx.x * 128;

    // ---- producer chunk tables (16B chunks; 1024 per operand) ----
    uint32_t sOff[4], gAo[4], gBo[4];
#pragma unroll
    for (int i = 0; i < 4; i++) {
        int c = tid + i * 256, row = c >> 3, ch = c & 7;
        sOff[i] = (uint32_t)((row * 8 + (ch ^ (row & 7))) * 16);
        gAo[i]  = (rowA0 + row) * (uint32_t)K + ch * 4;
        gBo[i]  = (rowB0 + row) * (uint32_t)K + ch * 4;
    }

    auto issue = [&](int fi) {
        const int s = fi % 3;
        const uint32_t k0 = (uint32_t)fi * 32;
        const uint32_t sA = sbase + s * STAGE_BY;
        const uint32_t sB = sA + A_BY;
#pragma unroll
        for (int i = 0; i < 4; i++) cp_async16(sA + sOff[i], Ah + gAo[i] + k0);
#pragma unroll
        for (int i = 0; i < 4; i++) cp_async16(sB + sOff[i], Bh + gBo[i] + k0);
        cp_commit();
    };

    // ---- consumer fragment addresses ----
    const int r8    = lane & 7;
    const int matId = lane >> 3;
    const int mrow  = ((matId & 1) << 3) + r8;
    const int mhi   = matId >> 1;
    uint32_t csw[4], aRow[4], bRow[2];
#pragma unroll
    for (int ks = 0; ks < 4; ks++) csw[ks] = (uint32_t)(((2 * ks + mhi) ^ r8) << 4);
#pragma unroll
    for (int t = 0; t < 4; t++) aRow[t] = (uint32_t)((wm * 64 + t * 16 + mrow) * 128);
#pragma unroll
    for (int t = 0; t < 2; t++) bRow[t] = (uint32_t)((wn * 32 + t * 16 + mrow) * 128) + A_BY;

    float acc[4][4][4];
#pragma unroll
    for (int mt = 0; mt < 4; mt++)
#pragma unroll
        for (int nt = 0; nt < 4; nt++)
#pragma unroll
            for (int q = 0; q < 4; q++) acc[mt][nt][q] = 0.0f;

    // ---- 3-stage pipeline ----
    issue(0);
    issue(1);

#pragma unroll 1
    for (int fi = 0; fi < nk; ++fi) {
        if (fi + 1 < nk) asm volatile("cp.async.wait_group 1;" ::: "memory");
        else             asm volatile("cp.async.wait_group 0;" ::: "memory");
        __syncthreads();
        if (fi + 2 < nk) issue(fi + 2);

        const uint32_t st = sbase + (fi % 3) * STAGE_BY;
#pragma unroll
        for (int ks = 0; ks < 4; ks++) {
            uint32_t a[4][4], bb[2][4];
#pragma unroll
            for (int mt = 0; mt < 4; mt++) ldsm4(a[mt],  st + aRow[mt] + csw[ks]);
#pragma unroll
            for (int np = 0; np < 2; np++) ldsm4(bb[np], st + bRow[np] + csw[ks]);
#pragma unroll
            for (int mt = 0; mt < 4; mt++)
#pragma unroll
                for (int nt = 0; nt < 4; nt++)
                    mma_tf32(acc[mt][nt], a[mt], bb[nt >> 1][nt & 1], bb[nt >> 1][2 + (nt & 1)]);
        }
    }

    // ---- epilogue: direct global stores (float2) ----
    const int gid = lane >> 2, tig = lane & 3;
#pragma unroll
    for (int mt = 0; mt < 4; mt++) {
        const int row = blockIdx.y * 128 + wm * 64 + mt * 16 + gid;
        float nr0 = 0.0f, nr8 = 0.0f;
        if (EPI == EPI_RBF) { nr0 = __ldg(e1 + row); nr8 = __ldg(e1 + row + 8); }
#pragma unroll
        for (int nt = 0; nt < 4; nt++) {
            const int col = blockIdx.x * 128 + wn * 32 + nt * 8 + tig * 2;
            float ec0 = 0.0f, ec1 = 0.0f;
            if (EPI == EPI_BIAS || EPI == EPI_BIAS_MISH || EPI == EPI_RBF) {
                const float* ee = (EPI == EPI_RBF) ? e2 : e1;
                ec0 = __ldg(ee + col); ec1 = __ldg(ee + col + 1);
            }
            float v[4] = {acc[mt][nt][0], acc[mt][nt][1], acc[mt][nt][2], acc[mt][nt][3]};
#pragma unroll
            for (int q = 0; q < 4; q++) {
                const float ec = (q & 1) ? ec1 : ec0;
                const float nr = (q < 2) ? nr0 : nr8;
                if (EPI == EPI_BIAS)           v[q] = v[q] + ec;
                else if (EPI == EPI_BIAS_MISH) v[q] = mish_f(v[q] + ec);
                else if (EPI == EPI_MISH)      v[q] = mish_f(v[q]);
                else if (EPI == EPI_RBF) {
                    float d2 = nr + ec - 2.0f * v[q];
                    v[q] = expf(-sqrtf(fmaxf(d2, 0.0f)));
                }
                if (STOREMODE == ST_ROUND) v[q] = tf32_rna(v[q]);
            }
            *(float2*)(Ch + (size_t)row * N + col)       = make_float2(v[0], v[1]);
            *(float2*)(Ch + (size_t)(row + 8) * N + col) = make_float2(v[2], v[3]);
        }
    }
}

// ---------------------------------------------------------------------------
// tf32 round copy + row squared-norms
// ---------------------------------------------------------------------------
__global__ void __launch_bounds__(256)
round_tf32_k(const float4* __restrict__ in, float4* __restrict__ out, int n4)
{
    int i = blockIdx.x * 256 + threadIdx.x;
    if (i < n4) {
        float4 v = in[i];
        v.x = tf32_rna(v.x); v.y = tf32_rna(v.y);
        v.z = tf32_rna(v.z); v.w = tf32_rna(v.w);
        out[i] = v;
    }
}

__global__ void __launch_bounds__(128)
rownorm2(const float* __restrict__ X, float* __restrict__ out)
{
    const int row = blockIdx.x;
    const float4 v = *((const float4*)(X + (size_t)row * ND) + threadIdx.x);
    float s = v.x * v.x + v.y * v.y + v.z * v.z + v.w * v.w;
#pragma unroll
    for (int o = 16; o; o >>= 1) s += __shfl_down_sync(0xffffffffu, s, o);
    __shared__ float ws[4];
    const int lane = threadIdx.x & 31, w = threadIdx.x >> 5;
    if (lane == 0) ws[w] = s;
    __syncthreads();
    if (threadIdx.x == 0) out[row] = ws[0] + ws[1] + ws[2] + ws[3];
}

// ---------------------------------------------------------------------------
// Launch — our launch index 3 (= global #5 with harness offset) is the fused
// dml layer-1 GEMM, for like-for-like profile comparison vs R6.
// ---------------------------------------------------------------------------
extern "C" void kernel_launch(void* const* d_in, const int* in_sizes, int n_in,
                              void* d_out, int out_size)
{
    const float* x   = (const float*)d_in[0];
    const float* sm  = (const float*)d_in[1];
    const float* W1  = (const float*)d_in[2];
    const float* b1  = (const float*)d_in[3];
    const float* W2  = (const float*)d_in[4];
    const float* b2  = (const float*)d_in[5];
    const float* Wn1 = (const float*)d_in[6];
    const float* Wn2 = (const float*)d_in[7];
    float* out = (float*)d_out;

    float *cat, *tmp1, *dml, *Kb, *Hb, *nrm, *rW1, *rW2, *rWn1, *rWn2;
    cudaGetSymbolAddress((void**)&cat,  g_cat);
    cudaGetSymbolAddress((void**)&tmp1, g_tmp1);
    cudaGetSymbolAddress((void**)&dml,  g_dml);
    cudaGetSymbolAddress((void**)&Kb,   g_K);
    cudaGetSymbolAddress((void**)&Hb,   g_H);
    cudaGetSymbolAddress((void**)&nrm,  g_nrm);
    cudaGetSymbolAddress((void**)&rW1,  g_rW1);
    cudaGetSymbolAddress((void**)&rW2,  g_rW2);
    cudaGetSymbolAddress((void**)&rWn1, g_rWn1);
    cudaGetSymbolAddress((void**)&rWn2, g_rWn2);

    cudaFuncSetAttribute(gemm_mma<EPI_BIAS_MISH, ST_ROUND>, cudaFuncAttributeMaxDynamicSharedMemorySize, DSMEM_BY);
    cudaFuncSetAttribute(gemm_mma<EPI_BIAS,      ST_ROUND>, cudaFuncAttributeMaxDynamicSharedMemorySize, DSMEM_BY);
    cudaFuncSetAttribute(gemm_mma<EPI_RBF,       ST_ROUND>, cudaFuncAttributeMaxDynamicSharedMemorySize, DSMEM_BY);
    cudaFuncSetAttribute(gemm_mma<EPI_MISH,      ST_ROUND>, cudaFuncAttributeMaxDynamicSharedMemorySize, DSMEM_BY);
    cudaFuncSetAttribute(gemm_mma<EPI_NONE,      ST_RAW  >, cudaFuncAttributeMaxDynamicSharedMemorySize, DSMEM_BY);

    const dim3 blk(256);

    // idx 0..2: rounding prerequisites for the profiled GEMM
    round_tf32_k<<<NB * ND / 4 / 256, 256>>>((const float4*)x,  (float4*)cat,             NB * ND / 4);
    round_tf32_k<<<NS * ND / 4 / 256, 256>>>((const float4*)sm, (float4*)(cat + NB * ND), NS * ND / 4);
    round_tf32_k<<<ND * ND / 4 / 256, 256>>>((const float4*)W1, (float4*)rW1,             ND * ND / 4);

    // idx 3: fused dml layer 1 — ncu capture target
    gemm_mma<EPI_BIAS_MISH, ST_ROUND><<<dim3(ND / 128, NM / 128), blk, DSMEM_BY>>>(
        cat, rW1, tmp1, NM, ND, ND, b1, nullptr);

    round_tf32_k<<<ND * ND / 4 / 256, 256>>>((const float4*)W2, (float4*)rW2, ND * ND / 4);

    // dml layer 2 (fused)
    gemm_mma<EPI_BIAS, ST_ROUND><<<dim3(ND / 128, NM / 128), blk, DSMEM_BY>>>(
        tmp1, rW2, dml, NM, ND, ND, b2, nullptr);
    rownorm2<<<NM, 128>>>(dml, nrm);

    round_tf32_k<<<NS * NS / 4 / 256, 256>>>((const float4*)Wn1, (float4*)rWn1, NS * NS / 4);

    // K = exp(-sqrt(max(nx + ns - 2*x_dml@sam^T, 0)))
    gemm_mma<EPI_RBF, ST_ROUND><<<dim3(NS / 128, NB / 128), blk, DSMEM_BY>>>(
        dml, dml + (size_t)NB * ND, Kb, NB, NS, ND, nrm, nrm + NB);

    // h = mish(K @ Wn1^T)
    gemm_mma<EPI_MISH, ST_ROUND><<<dim3(NS / 128, NB / 128), blk, DSMEM_BY>>>(
        Kb, rWn1, Hb, NB, NS, NS, nullptr, nullptr);

    round_tf32_k<<<NS * NS / 4 / 256, 256>>>((const float4*)Wn2, (float4*)rWn2, NS * NS / 4);

    // out = h @ Wn2^T
    gemm_mma<EPI_NONE, ST_RAW><<<dim3(NS / 128, NB / 128), blk, DSMEM_BY>>>(
        Hb, rWn2, out, NB, NS, NS, nullptr, nullptr);
}

// round 8
// speedup vs baseline: 1.5890x; 1.0263x over previous
#include <cuda_runtime.h>
#include <cstdint>
#include <math.h>

#define NB 16384
#define NS 2048
#define ND 512
#define NM (NB + NS)   // 18432 rows: [x ; samples]

// ---------------------------------------------------------------------------
// Scratch (__device__ globals — allocation-free contract)
// ---------------------------------------------------------------------------
__device__ __align__(16) float g_cat  [NM * ND];             // [rx ; rsm] rounded
__device__ __align__(16) float g_tmp1 [NM * ND];             // dml hidden
__device__ __align__(16) float g_dml  [NM * ND];             // [x_dml ; sam_new]
__device__ __align__(16) float g_K    [(long long)NB * NS];
__device__ __align__(16) float g_H    [(long long)NB * NS];
__device__ __align__(16) float g_nrm  [NM];                  // [nx ; ns]
__device__ __align__(16) float g_rW1  [ND * ND];
__device__ __align__(16) float g_rW2  [ND * ND];
__device__ __align__(16) float g_rWn1 [NS * NS];
__device__ __align__(16) float g_rWn2 [NS * NS];

// ---------------------------------------------------------------------------
// Helpers
// ---------------------------------------------------------------------------
__device__ __forceinline__ uint32_t smem_u32(const void* p) {
    uint32_t a;
    asm("{ .reg .u64 t; cvta.to.shared.u64 t, %1; cvt.u32.u64 %0, t; }" : "=r"(a) : "l"(p));
    return a;
}
__device__ __forceinline__ float tf32_rna(float x) {
    uint32_t r;
    asm("cvt.rna.tf32.f32 %0, %1;" : "=r"(r) : "f"(x));
    return __uint_as_float(r);
}
// Fast mish: tanh(log(w)) == (w^2-1)/(w^2+1), w = 1+e^z.
// MUFU ex2 + approx div instead of software log1pf+tanhf (~8 instr vs ~60).
// z>30 guard: w^2 overflows only past z~44; ratio is exactly 1.0f beyond z~8.7.
__device__ __forceinline__ float mish_f(float z) {
    float e  = __expf(z);
    float w  = 1.0f + e;
    float w2 = w * w;
    float r  = __fdividef(w2 - 1.0f, w2 + 1.0f);
    return (z > 30.0f) ? z : z * r;
}
__device__ __forceinline__ float rbf_f(float d2) {
    d2 = fmaxf(d2, 0.0f);
    float d;
    asm("sqrt.approx.f32 %0, %1;" : "=f"(d) : "f"(d2));
    return __expf(-d);
}
__device__ __forceinline__ void cp_async16(uint32_t saddr, const void* gaddr) {
    asm volatile("cp.async.cg.shared.global [%0], [%1], 16;" :: "r"(saddr), "l"(gaddr) : "memory");
}
__device__ __forceinline__ void cp_commit() {
    asm volatile("cp.async.commit_group;" ::: "memory");
}
__device__ __forceinline__ void ldsm4(uint32_t* d, uint32_t addr) {
    asm volatile("ldmatrix.sync.aligned.m8n8.x4.shared.b16 {%0,%1,%2,%3}, [%4];"
                 : "=r"(d[0]), "=r"(d[1]), "=r"(d[2]), "=r"(d[3]) : "r"(addr));
}
__device__ __forceinline__ void mma_tf32(float* c, const uint32_t* a, uint32_t b0, uint32_t b1) {
    asm volatile("mma.sync.aligned.m16n8k8.row.col.f32.tf32.tf32.f32 "
                 "{%0,%1,%2,%3}, {%4,%5,%6,%7}, {%8,%9}, {%0,%1,%2,%3};"
                 : "+f"(c[0]), "+f"(c[1]), "+f"(c[2]), "+f"(c[3])
                 : "r"(a[0]), "r"(a[1]), "r"(a[2]), "r"(a[3]), "r"(b0), "r"(b1));
}

enum { EPI_NONE = 0, EPI_BIAS = 1, EPI_BIAS_MISH = 2, EPI_MISH = 3, EPI_RBF = 4 };
enum { ST_RAW = 0, ST_ROUND = 1 };

// ---------------------------------------------------------------------------
// tf32 mma.sync GEMM:  C[M,N] = A[M,K] * B[N,K]^T (both row-major, K-major)
// CTA 128x128, 8 warps (2m x 4n) of 64x32 warp tiles. BK=32, 3-stage cp.async,
// 96KB smem -> 2 CTAs/SM (measured-best config).
// ---------------------------------------------------------------------------
#define A_BY     16384           // 128 rows * 128B
#define STAGE_BY 32768           // A + B
#define DSMEM_BY (3 * STAGE_BY)  // 98304

template <int EPI, int STOREMODE>
__global__ void __launch_bounds__(256, 2)
gemm_mma(const float* __restrict__ Ah, const float* __restrict__ Bh,
         float* __restrict__ Ch,
         int M, int N, int K,
         const float* __restrict__ e1, const float* __restrict__ e2)
{
    extern __shared__ float smem[];
    const uint32_t sbase = smem_u32(smem);

    const int tid  = threadIdx.x;
    const int wid  = tid >> 5;
    const int lane = tid & 31;
    const int wm   = wid & 1;        // 0..1 (64 rows each)
    const int wn   = wid >> 1;       // 0..3 (32 cols each)
    const int nk   = K >> 5;

    const uint32_t rowA0 = blockIdx.y * 128;
    const uint32_t rowB0 = blockIdx.x * 128;

    // ---- producer chunk tables (16B chunks; 1024 per operand) ----
    uint32_t sOff[4], gAo[4], gBo[4];
#pragma unroll
    for (int i = 0; i < 4; i++) {
        int c = tid + i * 256, row = c >> 3, ch = c & 7;
        sOff[i] = (uint32_t)((row * 8 + (ch ^ (row & 7))) * 16);
        gAo[i]  = (rowA0 + row) * (uint32_t)K + ch * 4;
        gBo[i]  = (rowB0 + row) * (uint32_t)K + ch * 4;
    }

    auto issue = [&](int fi) {
        const int s = fi % 3;
        const uint32_t k0 = (uint32_t)fi * 32;
        const uint32_t sA = sbase + s * STAGE_BY;
        const uint32_t sB = sA + A_BY;
#pragma unroll
        for (int i = 0; i < 4; i++) cp_async16(sA + sOff[i], Ah + gAo[i] + k0);
#pragma unroll
        for (int i = 0; i < 4; i++) cp_async16(sB + sOff[i], Bh + gBo[i] + k0);
        cp_commit();
    };

    // ---- consumer fragment addresses ----
    const int r8    = lane & 7;
    const int matId = lane >> 3;
    const int mrow  = ((matId & 1) << 3) + r8;
    const int mhi   = matId >> 1;
    uint32_t csw[4], aRow[4], bRow[2];
#pragma unroll
    for (int ks = 0; ks < 4; ks++) csw[ks] = (uint32_t)(((2 * ks + mhi) ^ r8) << 4);
#pragma unroll
    for (int t = 0; t < 4; t++) aRow[t] = (uint32_t)((wm * 64 + t * 16 + mrow) * 128);
#pragma unroll
    for (int t = 0; t < 2; t++) bRow[t] = (uint32_t)((wn * 32 + t * 16 + mrow) * 128) + A_BY;

    float acc[4][4][4];
#pragma unroll
    for (int mt = 0; mt < 4; mt++)
#pragma unroll
        for (int nt = 0; nt < 4; nt++)
#pragma unroll
            for (int q = 0; q < 4; q++) acc[mt][nt][q] = 0.0f;

    // ---- 3-stage pipeline ----
    issue(0);
    issue(1);

#pragma unroll 1
    for (int fi = 0; fi < nk; ++fi) {
        if (fi + 1 < nk) asm volatile("cp.async.wait_group 1;" ::: "memory");
        else             asm volatile("cp.async.wait_group 0;" ::: "memory");
        __syncthreads();
        if (fi + 2 < nk) issue(fi + 2);

        const uint32_t st = sbase + (fi % 3) * STAGE_BY;
#pragma unroll
        for (int ks = 0; ks < 4; ks++) {
            uint32_t a[4][4], bb[2][4];
#pragma unroll
            for (int mt = 0; mt < 4; mt++) ldsm4(a[mt],  st + aRow[mt] + csw[ks]);
#pragma unroll
            for (int np = 0; np < 2; np++) ldsm4(bb[np], st + bRow[np] + csw[ks]);
#pragma unroll
            for (int mt = 0; mt < 4; mt++)
#pragma unroll
                for (int nt = 0; nt < 4; nt++)
                    mma_tf32(acc[mt][nt], a[mt], bb[nt >> 1][nt & 1], bb[nt >> 1][2 + (nt & 1)]);
        }
    }

    // ---- epilogue: fast-math activations, direct float2 stores ----
    const int gid = lane >> 2, tig = lane & 3;
#pragma unroll
    for (int mt = 0; mt < 4; mt++) {
        const int row = blockIdx.y * 128 + wm * 64 + mt * 16 + gid;
        float nr0 = 0.0f, nr8 = 0.0f;
        if (EPI == EPI_RBF) { nr0 = __ldg(e1 + row); nr8 = __ldg(e1 + row + 8); }
#pragma unroll
        for (int nt = 0; nt < 4; nt++) {
            const int col = blockIdx.x * 128 + wn * 32 + nt * 8 + tig * 2;
            float ec0 = 0.0f, ec1 = 0.0f;
            if (EPI == EPI_BIAS || EPI == EPI_BIAS_MISH || EPI == EPI_RBF) {
                const float* ee = (EPI == EPI_RBF) ? e2 : e1;
                ec0 = __ldg(ee + col); ec1 = __ldg(ee + col + 1);
            }
            float v[4] = {acc[mt][nt][0], acc[mt][nt][1], acc[mt][nt][2], acc[mt][nt][3]};
#pragma unroll
            for (int q = 0; q < 4; q++) {
                const float ec = (q & 1) ? ec1 : ec0;
                const float nr = (q < 2) ? nr0 : nr8;
                if (EPI == EPI_BIAS)           v[q] = v[q] + ec;
                else if (EPI == EPI_BIAS_MISH) v[q] = mish_f(v[q] + ec);
                else if (EPI == EPI_MISH)      v[q] = mish_f(v[q]);
                else if (EPI == EPI_RBF)       v[q] = rbf_f(nr + ec - 2.0f * v[q]);
                if (STOREMODE == ST_ROUND) v[q] = tf32_rna(v[q]);
            }
            *(float2*)(Ch + (size_t)row * N + col)       = make_float2(v[0], v[1]);
            *(float2*)(Ch + (size_t)(row + 8) * N + col) = make_float2(v[2], v[3]);
        }
    }
}

// ---------------------------------------------------------------------------
// tf32 round copy + row squared-norms
// ---------------------------------------------------------------------------
__global__ void __launch_bounds__(256)
round_tf32_k(const float4* __restrict__ in, float4* __restrict__ out, int n4)
{
    int i = blockIdx.x * 256 + threadIdx.x;
    if (i < n4) {
        float4 v = in[i];
        v.x = tf32_rna(v.x); v.y = tf32_rna(v.y);
        v.z = tf32_rna(v.z); v.w = tf32_rna(v.w);
        out[i] = v;
    }
}

__global__ void __launch_bounds__(128)
rownorm2(const float* __restrict__ X, float* __restrict__ out)
{
    const int row = blockIdx.x;
    const float4 v = *((const float4*)(X + (size_t)row * ND) + threadIdx.x);
    float s = v.x * v.x + v.y * v.y + v.z * v.z + v.w * v.w;
#pragma unroll
    for (int o = 16; o; o >>= 1) s += __shfl_down_sync(0xffffffffu, s, o);
    __shared__ float ws[4];
    const int lane = threadIdx.x & 31, w = threadIdx.x >> 5;
    if (lane == 0) ws[w] = s;
    __syncthreads();
    if (threadIdx.x == 0) out[row] = ws[0] + ws[1] + ws[2] + ws[3];
}

// ---------------------------------------------------------------------------
// Launch — our launch index 3 (= ncu capture slot) stays the fused dml
// layer-1 GEMM for like-for-like comparison with R7 (74us, alu 41%).
// ---------------------------------------------------------------------------
extern "C" void kernel_launch(void* const* d_in, const int* in_sizes, int n_in,
                              void* d_out, int out_size)
{
    const float* x   = (const float*)d_in[0];
    const float* sm  = (const float*)d_in[1];
    const float* W1  = (const float*)d_in[2];
    const float* b1  = (const float*)d_in[3];
    const float* W2  = (const float*)d_in[4];
    const float* b2  = (const float*)d_in[5];
    const float* Wn1 = (const float*)d_in[6];
    const float* Wn2 = (const float*)d_in[7];
    float* out = (float*)d_out;

    float *cat, *tmp1, *dml, *Kb, *Hb, *nrm, *rW1, *rW2, *rWn1, *rWn2;
    cudaGetSymbolAddress((void**)&cat,  g_cat);
    cudaGetSymbolAddress((void**)&tmp1, g_tmp1);
    cudaGetSymbolAddress((void**)&dml,  g_dml);
    cudaGetSymbolAddress((void**)&Kb,   g_K);
    cudaGetSymbolAddress((void**)&Hb,   g_H);
    cudaGetSymbolAddress((void**)&nrm,  g_nrm);
    cudaGetSymbolAddress((void**)&rW1,  g_rW1);
    cudaGetSymbolAddress((void**)&rW2,  g_rW2);
    cudaGetSymbolAddress((void**)&rWn1, g_rWn1);
    cudaGetSymbolAddress((void**)&rWn2, g_rWn2);

    cudaFuncSetAttribute(gemm_mma<EPI_BIAS_MISH, ST_ROUND>, cudaFuncAttributeMaxDynamicSharedMemorySize, DSMEM_BY);
    cudaFuncSetAttribute(gemm_mma<EPI_BIAS,      ST_ROUND>, cudaFuncAttributeMaxDynamicSharedMemorySize, DSMEM_BY);
    cudaFuncSetAttribute(gemm_mma<EPI_RBF,       ST_ROUND>, cudaFuncAttributeMaxDynamicSharedMemorySize, DSMEM_BY);
    cudaFuncSetAttribute(gemm_mma<EPI_MISH,      ST_ROUND>, cudaFuncAttributeMaxDynamicSharedMemorySize, DSMEM_BY);
    cudaFuncSetAttribute(gemm_mma<EPI_NONE,      ST_RAW  >, cudaFuncAttributeMaxDynamicSharedMemorySize, DSMEM_BY);

    const dim3 blk(256);

    // idx 0..2: rounding prerequisites for the profiled GEMM
    round_tf32_k<<<NB * ND / 4 / 256, 256>>>((const float4*)x,  (float4*)cat,             NB * ND / 4);
    round_tf32_k<<<NS * ND / 4 / 256, 256>>>((const float4*)sm, (float4*)(cat + NB * ND), NS * ND / 4);
    round_tf32_k<<<ND * ND / 4 / 256, 256>>>((const float4*)W1, (float4*)rW1,             ND * ND / 4);

    // idx 3: fused dml layer 1 — ncu capture target
    gemm_mma<EPI_BIAS_MISH, ST_ROUND><<<dim3(ND / 128, NM / 128), blk, DSMEM_BY>>>(
        cat, rW1, tmp1, NM, ND, ND, b1, nullptr);

    round_tf32_k<<<ND * ND / 4 / 256, 256>>>((const float4*)W2, (float4*)rW2, ND * ND / 4);

    // dml layer 2 (fused)
    gemm_mma<EPI_BIAS, ST_ROUND><<<dim3(ND / 128, NM / 128), blk, DSMEM_BY>>>(
        tmp1, rW2, dml, NM, ND, ND, b2, nullptr);
    rownorm2<<<NM, 128>>>(dml, nrm);

    round_tf32_k<<<NS * NS / 4 / 256, 256>>>((const float4*)Wn1, (float4*)rWn1, NS * NS / 4);

    // K = exp(-sqrt(max(nx + ns - 2*x_dml@sam^T, 0)))
    gemm_mma<EPI_RBF, ST_ROUND><<<dim3(NS / 128, NB / 128), blk, DSMEM_BY>>>(
        dml, dml + (size_t)NB * ND, Kb, NB, NS, ND, nrm, nrm + NB);

    // h = mish(K @ Wn1^T)
    gemm_mma<EPI_MISH, ST_ROUND><<<dim3(NS / 128, NB / 128), blk, DSMEM_BY>>>(
        Kb, rWn1, Hb, NB, NS, NS, nullptr, nullptr);

    round_tf32_k<<<NS * NS / 4 / 256, 256>>>((const float4*)Wn2, (float4*)rWn2, NS * NS / 4);

    // out = h @ Wn2^T
    gemm_mma<EPI_NONE, ST_RAW><<<dim3(NS / 128, NB / 128), blk, DSMEM_BY>>>(
        Hb, rWn2, out, NB, NS, NS, nullptr, nullptr);
}